// round 5
// baseline (speedup 1.0000x reference)
#include <cuda_runtime.h>
#include <cuda_bf16.h>
#include <cstdint>

#define T_STEPS 4096
#define HID     1000
#define VOC     32000
#define G_CTAS  125
#define GM      4097
#define KAUG    3072            // 3 bf16 split terms
#define MPAD    4224            // 33 * 128
#define NBLKS   250
#define MBLKS   33
#define NCHUNK  48              // KAUG / 64
#define TILE_B  16384           // 128 rows * 128 bytes

// ---------------- device scratch (allocation-free rule) ----------------
__device__ __align__(256)  float              g_xseq[T_STEPS * HID];
__device__ __align__(256)  float              g_allh[(T_STEPS + 1) * HID];
__device__ __align__(256)  unsigned long long g_hbc[2][1024];   // {ts,val} packets
__device__ __align__(1024) char  g_A2T[(size_t)MBLKS * NCHUNK * TILE_B];
__device__ __align__(1024) char  g_B2T[(size_t)NBLKS * NCHUNK * TILE_B];

typedef unsigned long long ull;

__device__ __forceinline__ ull ld_acq64(const ull* p) {
    ull v;
    asm volatile("ld.acquire.gpu.u64 %0, [%1];" : "=l"(v) : "l"(p) : "memory");
    return v;
}
__device__ __forceinline__ void st_rel64(ull* p, ull v) {
    asm volatile("st.release.gpu.u64 [%0], %1;" :: "l"(p), "l"(v) : "memory");
}
__device__ __forceinline__ uint32_t smem_u32(const void* p) {
    uint32_t a;
    asm("{ .reg .u64 t; cvta.to.shared.u64 t, %1; cvt.u32.u64 %0, t; }" : "=r"(a) : "l"(p));
    return a;
}
#define SW128(off) ((off) ^ (((off) >> 3) & 0x70))

#define MBAR_INIT(a, c) asm volatile("mbarrier.init.shared.b64 [%0], %1;" :: "r"(a), "r"(c) : "memory")
#define MBAR_ARRIVE(a)  asm volatile("mbarrier.arrive.shared.b64 _, [%0];" :: "r"(a) : "memory")
#define MBAR_EXPECT_TX(a, n) asm volatile("mbarrier.arrive.expect_tx.shared.b64 _, [%0], %1;" :: "r"(a), "r"(n) : "memory")
#define MBAR_WAIT(a, ph) do {                                                    \
    uint32_t _m = (a), _p = (ph), _d;                                            \
    asm volatile("{\n\t.reg .pred p;\n\t"                                        \
        "mbarrier.try_wait.parity.acquire.cta.shared::cta.b64 p, [%1], %2;\n\t"  \
        "selp.b32 %0, 1, 0, p;\n\t}" : "=r"(_d) : "r"(_m), "r"(_p) : "memory");  \
    if (!_d) {                                                                   \
        asm volatile("{\n\t.reg .pred P1;\n\tWL_%=:\n\t"                         \
            "mbarrier.try_wait.parity.acquire.cta.shared::cta.b64 P1, [%0], %1, 0x989680;\n\t" \
            "@P1 bra.uni WD_%=;\n\tbra.uni WL_%=;\n\tWD_%=:\n\t}"                \
            :: "r"(_m), "r"(_p) : "memory");                                     \
    }                                                                            \
} while (0)

__device__ __forceinline__ void bulk_cp(uint32_t dst, const void* src,
                                        uint32_t bytes, uint32_t mbar) {
    asm volatile(
        "cp.async.bulk.shared::cta.global.mbarrier::complete_tx::bytes [%0], [%1], %2, [%3];"
        :: "r"(dst), "l"(src), "r"(bytes), "r"(mbar) : "memory");
}
__device__ __forceinline__ void ldsm_x4(uint32_t* r, uint32_t addr) {
    asm volatile("ldmatrix.sync.aligned.m8n8.x4.shared.b16 {%0,%1,%2,%3}, [%4];"
                 : "=r"(r[0]), "=r"(r[1]), "=r"(r[2]), "=r"(r[3]) : "r"(addr));
}
__device__ __forceinline__ void ldsm_x2(uint32_t* r, uint32_t addr) {
    asm volatile("ldmatrix.sync.aligned.m8n8.x2.shared.b16 {%0,%1}, [%2];"
                 : "=r"(r[0]), "=r"(r[1]) : "r"(addr));
}
__device__ __forceinline__ void mma_bf16(float* d, const uint32_t* a, const uint32_t* b) {
    asm volatile(
        "mma.sync.aligned.m16n8k16.row.col.f32.bf16.bf16.f32 "
        "{%0,%1,%2,%3}, {%4,%5,%6,%7}, {%8,%9}, {%0,%1,%2,%3};"
        : "+f"(d[0]), "+f"(d[1]), "+f"(d[2]), "+f"(d[3])
        : "r"(a[0]), "r"(a[1]), "r"(a[2]), "r"(a[3]), "r"(b[0]), "r"(b[1]));
}

// ---------------------------------------------------------------------------
// Kernel 1: gather x_seq = W_xh[:, tok[t]]  (+ init all_h[0], h packets)
// ---------------------------------------------------------------------------
__global__ void gather_kernel(const int* __restrict__ tok,
                              const float* __restrict__ Wxh,
                              const float* __restrict__ h0) {
    int i = blockIdx.x * blockDim.x + threadIdx.x;
    if (i < T_STEPS * HID) {
        int t = i / HID;
        int h = i - t * HID;
        g_xseq[i] = __ldg(&Wxh[(long long)h * VOC + tok[t]]);
    }
    if (i < 1024) {
        float v = (i < HID) ? h0[i] : 0.0f;
        if (i < HID) g_allh[i] = v;
        g_hbc[0][i] = (ull)__float_as_uint(v);   // ts=0, value=h0
        g_hbc[1][i] = 0ull;                      // ts=0 (any ts < 1)
    }
}

// ---------------------------------------------------------------------------
// Kernel 2: persistent RNN scan — data-embedded timestamps, parity slots.
// ---------------------------------------------------------------------------
__global__ __launch_bounds__(256, 1)
void scan_kernel(const float* __restrict__ Whh,
                 const float* __restrict__ Bh) {
    __shared__ float hs[1024];
    const int tid  = threadIdx.x;
    const int warp = tid >> 5;
    const int lane = tid & 31;
    const int row  = blockIdx.x * 8 + warp;

    float w[8][4];
#pragma unroll
    for (int j = 0; j < 8; j++)
#pragma unroll
        for (int q = 0; q < 4; q++) {
            int k = 4 * lane + q + 128 * j;
            w[j][q] = (k < HID) ? __ldg(&Whh[row * HID + k]) : 0.0f;
        }
    const float bias = __ldg(&Bh[row]);

    if (tid >= 250) ((float4*)hs)[tid] = make_float4(0.f, 0.f, 0.f, 0.f); // pad once

    for (int t = 0; t < T_STEPS; t++) {
        float xv = 0.0f;
        if (lane == 0) xv = __ldg(&g_xseq[t * HID + row]);   // prefetch

        if (tid < 250) {
            const ull* slot = g_hbc[t & 1] + 4 * tid;
            ull v0, v1, v2, v3;
            const unsigned ts = (unsigned)t;
            do {
                v0 = ld_acq64(slot + 0);
                v1 = ld_acq64(slot + 1);
                v2 = ld_acq64(slot + 2);
                v3 = ld_acq64(slot + 3);
            } while ((unsigned)(v0 >> 32) < ts || (unsigned)(v1 >> 32) < ts ||
                     (unsigned)(v2 >> 32) < ts || (unsigned)(v3 >> 32) < ts);
            hs[4 * tid + 0] = __uint_as_float((unsigned)v0);
            hs[4 * tid + 1] = __uint_as_float((unsigned)v1);
            hs[4 * tid + 2] = __uint_as_float((unsigned)v2);
            hs[4 * tid + 3] = __uint_as_float((unsigned)v3);
        }
        __syncthreads();

        float a0 = 0.f, a1 = 0.f, a2 = 0.f, a3 = 0.f;
#pragma unroll
        for (int j = 0; j < 8; j++) {
            float4 hv = ((const float4*)hs)[lane + 32 * j];
            a0 = fmaf(w[j][0], hv.x, a0);
            a1 = fmaf(w[j][1], hv.y, a1);
            a2 = fmaf(w[j][2], hv.z, a2);
            a3 = fmaf(w[j][3], hv.w, a3);
        }
        float acc = (a0 + a1) + (a2 + a3);
#pragma unroll
        for (int s = 16; s > 0; s >>= 1)
            acc += __shfl_xor_sync(0xffffffffu, acc, s);

        if (lane == 0) {
            float y = tanhf(acc + xv + bias);
            g_allh[(size_t)(t + 1) * HID + row] = y;
            st_rel64(&g_hbc[(t + 1) & 1][row],
                     ((ull)(unsigned)(t + 1) << 32) | (ull)__float_as_uint(y));
        }
        __syncthreads();   // hs reuse guard
    }
}

// ---------------------------------------------------------------------------
// Kernels 3a/3b: fp32 -> bf16 split, tiled pre-swizzled, 16B granules.
//   A' terms: [Ah | Ah | Al]   B' terms: [Bh | Bl | Bh]
// ---------------------------------------------------------------------------
__device__ __forceinline__ uint4 granule(const float* __restrict__ src,
                                         bool valid, bool lo) {
    float v[8];
    if (valid) {
        float4 u0 = *(const float4*)src;
        float4 u1 = *(const float4*)(src + 4);
        v[0]=u0.x; v[1]=u0.y; v[2]=u0.z; v[3]=u0.w;
        v[4]=u1.x; v[5]=u1.y; v[6]=u1.z; v[7]=u1.w;
    } else {
#pragma unroll
        for (int j = 0; j < 8; j++) v[j] = 0.f;
    }
    uint32_t p[4];
#pragma unroll
    for (int j = 0; j < 4; j++) {
        float a = v[2*j], b = v[2*j+1];
        if (lo) {
            a -= __bfloat162float(__float2bfloat16(a));
            b -= __bfloat162float(__float2bfloat16(b));
        }
        __nv_bfloat162 h = __floats2bfloat162_rn(a, b);   // low=a, high=b
        p[j] = *(uint32_t*)&h;
    }
    return make_uint4(p[0], p[1], p[2], p[3]);
}

__global__ void convertA_kernel() {
    int i = blockIdx.x * blockDim.x + threadIdx.x;
    if (i >= MBLKS * NCHUNK * 1024) return;
    int tileId = i >> 10;
    int e = i & 1023;
    int r = e >> 3, cg = e & 7;
    int mblk = tileId / NCHUNK, chunk = tileId - mblk * NCHUNK;
    int kp = chunk * 64 + cg * 8;
    int term = kp >> 10, k = kp & 1023;
    int m = mblk * 128 + r;
    bool valid = (m < GM) && (k < HID);
    uint4 g = granule(g_allh + (size_t)m * HID + k, valid, term == 2);
    uint32_t off = SW128((uint32_t)(r * 128 + cg * 16));
    *(uint4*)(g_A2T + (size_t)tileId * TILE_B + off) = g;
}

__global__ void convertB_kernel(const float* __restrict__ Why) {
    int i = blockIdx.x * blockDim.x + threadIdx.x;
    if (i >= NBLKS * NCHUNK * 1024) return;
    int tileId = i >> 10;
    int e = i & 1023;
    int r = e >> 3, cg = e & 7;
    int nblk = tileId / NCHUNK, chunk = tileId - nblk * NCHUNK;
    int kp = chunk * 64 + cg * 8;
    int term = kp >> 10, k = kp & 1023;
    int n = nblk * 128 + r;
    bool valid = (k < HID);
    uint4 g = granule(Why + (size_t)n * HID + k, valid, term == 1);
    uint32_t off = SW128((uint32_t)(r * 128 + cg * 16));
    *(uint4*)(g_B2T + (size_t)tileId * TILE_B + off) = g;
}

// ---------------------------------------------------------------------------
// Kernel 4: HMMA GEMM fed by cp.async.bulk (unchanged from R4).
// ---------------------------------------------------------------------------
#define NSTAGE 4
#define STAGE_BYTES (2 * TILE_B)
#define GEMM_SMEM (2048 + NSTAGE * STAGE_BYTES)

__global__ __launch_bounds__(256, 1)
void gemm_bulk_kernel(float* __restrict__ C) {
    extern __shared__ char dsm[];
    const uint32_t raw   = smem_u32(dsm);
    const uint32_t fullb = raw;
    const uint32_t emptb = raw + 64;
    const uint32_t tiles = (raw + 1024 + 1023) & ~1023u;

    const int tid  = threadIdx.x;
    const int wid  = tid >> 5;
    const int lane = tid & 31;
    const int wm   = wid >> 2;
    const int wn   = wid & 3;
    const int mblk = blockIdx.x;
    const int nblk = blockIdx.y;
    const int m0   = mblk * 128;
    const int n0   = nblk * 128;

    if (tid == 0) {
#pragma unroll
        for (int s = 0; s < NSTAGE; s++) {
            MBAR_INIT(fullb + 8 * s, 1);
            MBAR_INIT(emptb + 8 * s, 256);
        }
    }
    __syncthreads();

    const char* Abase = g_A2T + (size_t)mblk * NCHUNK * TILE_B;
    const char* Bbase = g_B2T + (size_t)nblk * NCHUNK * TILE_B;

    if (tid == 0) {
#pragma unroll
        for (int i = 0; i < NSTAGE; i++) {
            uint32_t mb = fullb + 8 * i;
            MBAR_EXPECT_TX(mb, STAGE_BYTES);
            bulk_cp(tiles + i * STAGE_BYTES,          Abase + (size_t)i * TILE_B, TILE_B, mb);
            bulk_cp(tiles + i * STAGE_BYTES + TILE_B, Bbase + (size_t)i * TILE_B, TILE_B, mb);
        }
    }

    float acc[4][4][4];
#pragma unroll
    for (int i = 0; i < 4; i++)
#pragma unroll
        for (int j = 0; j < 4; j++)
#pragma unroll
            for (int q = 0; q < 4; q++) acc[i][j][q] = 0.f;

    const uint32_t a_row = (uint32_t)(wm * 64 + (lane & 15));
    const uint32_t a_k   = (uint32_t)((lane >> 4) * 8);
    const uint32_t b_row = (uint32_t)(wn * 32 + (lane & 7));
    const uint32_t b_k   = (uint32_t)(((lane >> 3) & 1) * 8);

    for (int i = 0; i < NCHUNK; i++) {
        const int s = i & 3;
        MBAR_WAIT(fullb + 8 * s, (i >> 2) & 1);

        const uint32_t sA = tiles + s * STAGE_BYTES;
        const uint32_t sB = sA + TILE_B;
#pragma unroll
        for (int ks = 0; ks < 4; ks++) {
            uint32_t a[4][4], b[4][2];
#pragma unroll
            for (int fm = 0; fm < 4; fm++) {
                uint32_t off = (a_row + fm * 16) * 128 + (ks * 16 + a_k) * 2;
                ldsm_x4(a[fm], sA + SW128(off));
            }
#pragma unroll
            for (int fn = 0; fn < 4; fn++) {
                uint32_t off = (b_row + fn * 8) * 128 + (ks * 16 + b_k) * 2;
                ldsm_x2(b[fn], sB + SW128(off));
            }
#pragma unroll
            for (int fm = 0; fm < 4; fm++)
#pragma unroll
                for (int fn = 0; fn < 4; fn++)
                    mma_bf16(acc[fm][fn], a[fm], b[fn]);
        }
        MBAR_ARRIVE(emptb + 8 * s);

        if (tid == 0 && i + NSTAGE < NCHUNK) {
            MBAR_WAIT(emptb + 8 * s, (i >> 2) & 1);
            const int j = i + NSTAGE;
            uint32_t mb = fullb + 8 * s;
            MBAR_EXPECT_TX(mb, STAGE_BYTES);
            bulk_cp(tiles + s * STAGE_BYTES,          Abase + (size_t)j * TILE_B, TILE_B, mb);
            bulk_cp(tiles + s * STAGE_BYTES + TILE_B, Bbase + (size_t)j * TILE_B, TILE_B, mb);
        }
    }

    const int er = lane >> 2;
    const int ec = (lane & 3) * 2;
#pragma unroll
    for (int fm = 0; fm < 4; fm++) {
        int r0 = m0 + wm * 64 + fm * 16 + er;
#pragma unroll
        for (int fn = 0; fn < 4; fn++) {
            int c = n0 + wn * 32 + fn * 8 + ec;
            if (r0 < GM)
                *(float2*)(C + (size_t)r0 * VOC + c) = make_float2(acc[fm][fn][0], acc[fm][fn][1]);
            if (r0 + 8 < GM)
                *(float2*)(C + (size_t)(r0 + 8) * VOC + c) = make_float2(acc[fm][fn][2], acc[fm][fn][3]);
        }
    }
}

// ---------------------------------------------------------------------------
extern "C" void kernel_launch(void* const* d_in, const int* in_sizes, int n_in,
                              void* d_out, int out_size) {
    const int*   tok = (const int*)  d_in[0];
    const float* h0  = (const float*)d_in[1];
    const float* Wxh = (const float*)d_in[2];
    const float* Whh = (const float*)d_in[3];
    const float* Why = (const float*)d_in[4];
    const float* Bh  = (const float*)d_in[5];
    float* out = (float*)d_out;

    gather_kernel<<<(T_STEPS * HID + 255) / 256, 256>>>(tok, Wxh, h0);
    convertB_kernel<<<(NBLKS * NCHUNK * 1024 + 255) / 256, 256>>>(Why);
    scan_kernel<<<G_CTAS, 256>>>(Whh, Bh);
    convertA_kernel<<<(MBLKS * NCHUNK * 1024 + 255) / 256, 256>>>();

    cudaFuncSetAttribute(gemm_bulk_kernel,
                         cudaFuncAttributeMaxDynamicSharedMemorySize, GEMM_SMEM);
    dim3 ggrid(MBLKS, NBLKS);
    gemm_bulk_kernel<<<ggrid, 256, GEMM_SMEM>>>(out);
}

// round 6
// speedup vs baseline: 1.1154x; 1.1154x over previous
#include <cuda_runtime.h>
#include <cuda_bf16.h>
#include <cstdint>

#define T_STEPS 4096
#define HID     1000
#define VOC     32000
#define G_CTAS  125
#define GM      4097
#define NBLKS   250
#define MBLKS   33
#define NCHUNK  48              // 3072 / 64
#define TILE_B  16384           // 128 rows * 128 bytes

// ---------------- device scratch (allocation-free rule) ----------------
__device__ __align__(256)  float g_xseq[T_STEPS * HID];
__device__ __align__(256)  float g_allh[(T_STEPS + 1) * HID];
__device__ __align__(1024) char  g_A2T[(size_t)MBLKS * NCHUNK * TILE_B];
__device__ __align__(1024) char  g_B2T[(size_t)NBLKS * NCHUNK * TILE_B];
__device__ unsigned g_flags[G_CTAS * 32];   // one flag per 128B line

__device__ __forceinline__ unsigned ld_acquire(const unsigned* p) {
    unsigned v;
    asm volatile("ld.acquire.gpu.u32 %0, [%1];" : "=r"(v) : "l"(p) : "memory");
    return v;
}
__device__ __forceinline__ void st_release(unsigned* p, unsigned v) {
    asm volatile("st.release.gpu.u32 [%0], %1;" :: "l"(p), "r"(v) : "memory");
}
__device__ __forceinline__ uint32_t smem_u32(const void* p) {
    uint32_t a;
    asm("{ .reg .u64 t; cvta.to.shared.u64 t, %1; cvt.u32.u64 %0, t; }" : "=r"(a) : "l"(p));
    return a;
}
#define SW128(off) ((off) ^ (((off) >> 3) & 0x70))

#define MBAR_INIT(a, c) asm volatile("mbarrier.init.shared.b64 [%0], %1;" :: "r"(a), "r"(c) : "memory")
#define MBAR_ARRIVE(a)  asm volatile("mbarrier.arrive.shared.b64 _, [%0];" :: "r"(a) : "memory")
#define MBAR_EXPECT_TX(a, n) asm volatile("mbarrier.arrive.expect_tx.shared.b64 _, [%0], %1;" :: "r"(a), "r"(n) : "memory")
#define MBAR_WAIT(a, ph) do {                                                    \
    uint32_t _m = (a), _p = (ph), _d;                                            \
    asm volatile("{\n\t.reg .pred p;\n\t"                                        \
        "mbarrier.try_wait.parity.acquire.cta.shared::cta.b64 p, [%1], %2;\n\t"  \
        "selp.b32 %0, 1, 0, p;\n\t}" : "=r"(_d) : "r"(_m), "r"(_p) : "memory");  \
    if (!_d) {                                                                   \
        asm volatile("{\n\t.reg .pred P1;\n\tWL_%=:\n\t"                         \
            "mbarrier.try_wait.parity.acquire.cta.shared::cta.b64 P1, [%0], %1, 0x989680;\n\t" \
            "@P1 bra.uni WD_%=;\n\tbra.uni WL_%=;\n\tWD_%=:\n\t}"                \
            :: "r"(_m), "r"(_p) : "memory");                                     \
    }                                                                            \
} while (0)

__device__ __forceinline__ void bulk_cp(uint32_t dst, const void* src,
                                        uint32_t bytes, uint32_t mbar) {
    asm volatile(
        "cp.async.bulk.shared::cta.global.mbarrier::complete_tx::bytes [%0], [%1], %2, [%3];"
        :: "r"(dst), "l"(src), "r"(bytes), "r"(mbar) : "memory");
}
__device__ __forceinline__ void ldsm_x4(uint32_t* r, uint32_t addr) {
    asm volatile("ldmatrix.sync.aligned.m8n8.x4.shared.b16 {%0,%1,%2,%3}, [%4];"
                 : "=r"(r[0]), "=r"(r[1]), "=r"(r[2]), "=r"(r[3]) : "r"(addr));
}
__device__ __forceinline__ void ldsm_x2(uint32_t* r, uint32_t addr) {
    asm volatile("ldmatrix.sync.aligned.m8n8.x2.shared.b16 {%0,%1}, [%2];"
                 : "=r"(r[0]), "=r"(r[1]) : "r"(addr));
}
__device__ __forceinline__ void mma_bf16(float* d, const uint32_t* a, const uint32_t* b) {
    asm volatile(
        "mma.sync.aligned.m16n8k16.row.col.f32.bf16.bf16.f32 "
        "{%0,%1,%2,%3}, {%4,%5,%6,%7}, {%8,%9}, {%0,%1,%2,%3};"
        : "+f"(d[0]), "+f"(d[1]), "+f"(d[2]), "+f"(d[3])
        : "r"(a[0]), "r"(a[1]), "r"(a[2]), "r"(a[3]), "r"(b[0]), "r"(b[1]));
}

// A' tile store helper: row m (tile row r, block mb), k-position kp, bf16 value
__device__ __forceinline__ void storeA(int mb, int r, int kp, __nv_bfloat16 v) {
    char* t = g_A2T + ((size_t)mb * NCHUNK + (kp >> 6)) * TILE_B;
    *(__nv_bfloat16*)(t + SW128((uint32_t)(r * 128 + (kp & 63) * 2))) = v;
}

// ---------------------------------------------------------------------------
// Kernel 1: gather x_seq, init all_h[0] + A' row 0, reset flags
// ---------------------------------------------------------------------------
__global__ void gather_kernel(const int* __restrict__ tok,
                              const float* __restrict__ Wxh,
                              const float* __restrict__ h0) {
    int i = blockIdx.x * blockDim.x + threadIdx.x;
    if (i < T_STEPS * HID) {
        int t = i / HID;
        int h = i - t * HID;
        g_xseq[i] = __ldg(&Wxh[(long long)h * VOC + tok[t]]);
    }
    if (i < G_CTAS * 32) g_flags[i] = 0u;
    if (i < HID) {
        float v = h0[i];
        g_allh[i] = v;
        __nv_bfloat16 hi = __float2bfloat16(v);
        __nv_bfloat16 lo = __float2bfloat16(v - __bfloat162float(hi));
        storeA(0, 0, i, hi);
        storeA(0, 0, 1024 + i, hi);
        storeA(0, 0, 2048 + i, lo);
    }
}

// ---------------------------------------------------------------------------
// Kernel 2: fp32 -> bf16 split of W_hy, tiled pre-swizzled (16B granules).
//   B' terms: [Bh | Bl | Bh]
// ---------------------------------------------------------------------------
__global__ void convertB_kernel(const float* __restrict__ Why) {
    int i = blockIdx.x * blockDim.x + threadIdx.x;
    if (i >= NBLKS * NCHUNK * 1024) return;
    int tileId = i >> 10;
    int e = i & 1023;
    int r = e >> 3, cg = e & 7;
    int nblk = tileId / NCHUNK, chunk = tileId - nblk * NCHUNK;
    int kp = chunk * 64 + cg * 8;
    int term = kp >> 10, k = kp & 1023;
    int n = nblk * 128 + r;
    bool lo = (term == 1);
    float v[8];
    if (k < HID) {
        float4 u0 = *(const float4*)(Why + (size_t)n * HID + k);
        float4 u1 = *(const float4*)(Why + (size_t)n * HID + k + 4);
        v[0]=u0.x; v[1]=u0.y; v[2]=u0.z; v[3]=u0.w;
        v[4]=u1.x; v[5]=u1.y; v[6]=u1.z; v[7]=u1.w;
    } else {
#pragma unroll
        for (int j = 0; j < 8; j++) v[j] = 0.f;
    }
    uint32_t p[4];
#pragma unroll
    for (int j = 0; j < 4; j++) {
        float a = v[2*j], b = v[2*j+1];
        if (lo) {
            a -= __bfloat162float(__float2bfloat16(a));
            b -= __bfloat162float(__float2bfloat16(b));
        }
        __nv_bfloat162 h = __floats2bfloat162_rn(a, b);
        p[j] = *(uint32_t*)&h;
    }
    uint32_t off = SW128((uint32_t)(r * 128 + cg * 16));
    *(uint4*)(g_B2T + (size_t)tileId * TILE_B + off) = make_uint4(p[0], p[1], p[2], p[3]);
}

// ---------------------------------------------------------------------------
// Kernel 3 (FUSED): bids [0,125) = persistent RNN scan (R4 comm scheme,
// + direct bf16 A' tile stores).  bids [125, 125+8250) = HMMA GEMM CTAs,
// mblk-ascending, gated on scan progress flags.  Deadlock-free: scan CTAs
// are the lowest bids -> guaranteed wave-1 residency; they wait on nobody.
// ---------------------------------------------------------------------------
#define NSTAGE 3
#define STAGE_BYTES (2 * TILE_B)
#define GEMM_SMEM (1024 + NSTAGE * STAGE_BYTES)     // 99328 dynamic

__global__ __launch_bounds__(256, 2)
void fused_kernel(const float* __restrict__ Whh,
                  const float* __restrict__ Bh,
                  float* __restrict__ C) {
    __shared__ float hs[1024];
    extern __shared__ char dsm[];
    const int tid  = threadIdx.x;
    const int wid  = tid >> 5;
    const int lane = tid & 31;

    if (blockIdx.x < G_CTAS) {
        // ================= SCAN =================
        const int row = blockIdx.x * 8 + wid;
        float w[8][4];
#pragma unroll
        for (int j = 0; j < 8; j++)
#pragma unroll
            for (int q = 0; q < 4; q++) {
                int k = 4 * lane + q + 128 * j;
                w[j][q] = (k < HID) ? __ldg(&Whh[row * HID + k]) : 0.0f;
            }
        const float bias = __ldg(&Bh[row]);
        const float4* __restrict__ allh4 = (const float4*)g_allh;
        if (tid >= 250) ((float4*)hs)[tid] = make_float4(0.f, 0.f, 0.f, 0.f);

        for (int t = 0; t < T_STEPS; t++) {
            float xv = 0.0f;
            if (lane == 0) xv = __ldg(&g_xseq[t * HID + row]);

            if (t > 0 && tid < G_CTAS) {
                while (ld_acquire(&g_flags[tid * 32]) < (unsigned)t) { }
            }
            __syncthreads();

            if (tid < 250)
                ((float4*)hs)[tid] = __ldcg(allh4 + (size_t)t * 250 + tid);
            __syncthreads();

            float a0 = 0.f, a1 = 0.f, a2 = 0.f, a3 = 0.f;
#pragma unroll
            for (int j = 0; j < 8; j++) {
                float4 hv = ((const float4*)hs)[lane + 32 * j];
                a0 = fmaf(w[j][0], hv.x, a0);
                a1 = fmaf(w[j][1], hv.y, a1);
                a2 = fmaf(w[j][2], hv.z, a2);
                a3 = fmaf(w[j][3], hv.w, a3);
            }
            float acc = (a0 + a1) + (a2 + a3);
#pragma unroll
            for (int s = 16; s > 0; s >>= 1)
                acc += __shfl_xor_sync(0xffffffffu, acc, s);

            if (lane == 0) {
                float y = tanhf(acc + xv + bias);
                int m = t + 1;
                g_allh[(size_t)m * HID + row] = y;
                __nv_bfloat16 hi = __float2bfloat16(y);
                __nv_bfloat16 lo = __float2bfloat16(y - __bfloat162float(hi));
                int mb = m >> 7, r = m & 127;
                storeA(mb, r, row, hi);
                storeA(mb, r, 1024 + row, hi);
                storeA(mb, r, 2048 + row, lo);
            }
            __syncthreads();
            if (tid == 0) st_release(&g_flags[blockIdx.x * 32], (unsigned)(t + 1));
        }
        return;
    }

    // ================= GEMM =================
    const int g    = blockIdx.x - G_CTAS;
    const int mblk = g / NBLKS;
    const int nblk = g - mblk * NBLKS;
    const int m0   = mblk * 128;
    const int n0   = nblk * 128;

    const uint32_t raw   = smem_u32(dsm);
    const uint32_t fullb = raw;
    const uint32_t emptb = raw + 64;
    const uint32_t tiles = (raw + 1024 + 1023) & ~1023u;

    if (tid == 0) {
#pragma unroll
        for (int s = 0; s < NSTAGE; s++) {
            MBAR_INIT(fullb + 8 * s, 1);
            MBAR_INIT(emptb + 8 * s, 256);
        }
    }
    __syncthreads();

    // gate: all 125 scan CTAs must have produced rows [m0, m0+127]
    {
        unsigned need = (unsigned)(m0 + 127 < 4096 ? m0 + 127 : 4096);
        if (tid < G_CTAS) {
            while (ld_acquire(&g_flags[tid * 32]) < need) __nanosleep(256);
        }
        __syncthreads();
    }

    const char* Abase = g_A2T + (size_t)mblk * NCHUNK * TILE_B;
    const char* Bbase = g_B2T + (size_t)nblk * NCHUNK * TILE_B;

    if (tid == 0) {
#pragma unroll
        for (int i = 0; i < NSTAGE; i++) {
            uint32_t mb = fullb + 8 * i;
            MBAR_EXPECT_TX(mb, STAGE_BYTES);
            bulk_cp(tiles + i * STAGE_BYTES,          Abase + (size_t)i * TILE_B, TILE_B, mb);
            bulk_cp(tiles + i * STAGE_BYTES + TILE_B, Bbase + (size_t)i * TILE_B, TILE_B, mb);
        }
    }

    float acc[4][4][4];
#pragma unroll
    for (int i = 0; i < 4; i++)
#pragma unroll
        for (int j = 0; j < 4; j++)
#pragma unroll
            for (int q = 0; q < 4; q++) acc[i][j][q] = 0.f;

    const int wm = wid >> 2;
    const int wn = wid & 3;
    const uint32_t a_row = (uint32_t)(wm * 64 + (lane & 15));
    const uint32_t a_k   = (uint32_t)((lane >> 4) * 8);
    const uint32_t b_row = (uint32_t)(wn * 32 + (lane & 7));
    const uint32_t b_k   = (uint32_t)(((lane >> 3) & 1) * 8);

    int s = 0, ph = 0;
    for (int i = 0; i < NCHUNK; i++) {
        MBAR_WAIT(fullb + 8 * s, ph);

        const uint32_t sA = tiles + s * STAGE_BYTES;
        const uint32_t sB = sA + TILE_B;
#pragma unroll
        for (int ks = 0; ks < 4; ks++) {
            uint32_t a[4][4], b[4][2];
#pragma unroll
            for (int fm = 0; fm < 4; fm++) {
                uint32_t off = (a_row + fm * 16) * 128 + (ks * 16 + a_k) * 2;
                ldsm_x4(a[fm], sA + SW128(off));
            }
#pragma unroll
            for (int fn = 0; fn < 4; fn++) {
                uint32_t off = (b_row + fn * 8) * 128 + (ks * 16 + b_k) * 2;
                ldsm_x2(b[fn], sB + SW128(off));
            }
#pragma unroll
            for (int fm = 0; fm < 4; fm++)
#pragma unroll
                for (int fn = 0; fn < 4; fn++)
                    mma_bf16(acc[fm][fn], a[fm], b[fn]);
        }
        MBAR_ARRIVE(emptb + 8 * s);

        if (tid == 0 && i + NSTAGE < NCHUNK) {
            MBAR_WAIT(emptb + 8 * s, ph);
            const int j = i + NSTAGE;
            uint32_t mb = fullb + 8 * s;
            MBAR_EXPECT_TX(mb, STAGE_BYTES);
            bulk_cp(tiles + s * STAGE_BYTES,          Abase + (size_t)j * TILE_B, TILE_B, mb);
            bulk_cp(tiles + s * STAGE_BYTES + TILE_B, Bbase + (size_t)j * TILE_B, TILE_B, mb);
        }
        if (++s == NSTAGE) { s = 0; ph ^= 1; }
    }

    const int er = lane >> 2;
    const int ec = (lane & 3) * 2;
#pragma unroll
    for (int fm = 0; fm < 4; fm++) {
        int r0 = m0 + wm * 64 + fm * 16 + er;
#pragma unroll
        for (int fn = 0; fn < 4; fn++) {
            int c = n0 + wn * 32 + fn * 8 + ec;
            if (r0 < GM)
                *(float2*)(C + (size_t)r0 * VOC + c) = make_float2(acc[fm][fn][0], acc[fm][fn][1]);
            if (r0 + 8 < GM)
                *(float2*)(C + (size_t)(r0 + 8) * VOC + c) = make_float2(acc[fm][fn][2], acc[fm][fn][3]);
        }
    }
}

// ---------------------------------------------------------------------------
extern "C" void kernel_launch(void* const* d_in, const int* in_sizes, int n_in,
                              void* d_out, int out_size) {
    const int*   tok = (const int*)  d_in[0];
    const float* h0  = (const float*)d_in[1];
    const float* Wxh = (const float*)d_in[2];
    const float* Whh = (const float*)d_in[3];
    const float* Why = (const float*)d_in[4];
    const float* Bh  = (const float*)d_in[5];
    float* out = (float*)d_out;

    gather_kernel<<<(T_STEPS * HID + 255) / 256, 256>>>(tok, Wxh, h0);
    convertB_kernel<<<(NBLKS * NCHUNK * 1024 + 255) / 256, 256>>>(Why);

    cudaFuncSetAttribute(fused_kernel,
                         cudaFuncAttributeMaxDynamicSharedMemorySize, GEMM_SMEM);
    fused_kernel<<<G_CTAS + MBLKS * NBLKS, 256, GEMM_SMEM>>>(Whh, Bh, out);
}